// round 5
// baseline (speedup 1.0000x reference)
#include <cuda_runtime.h>
#include <cuda_bf16.h>
#include <cstdint>

typedef unsigned long long ull;

// ---------------- problem constants ----------------
#define BATCH 64
#define DIN   176
#define HID   512
#define G4    2048          // 4*HID
#define T_ENC 1025          // 1 + 1024
#define T_DEC 1023          // TTGT - 1
#define MROWS_MAX (BATCH * T_ENC)   // 65600

// ---------------- scratch (static device globals; no cudaMalloc allowed) ----
__device__ float g_gx  [(size_t)MROWS_MAX * G4];   // per-layer gx, also reused as hmid
__device__ float g_seqA[(size_t)MROWS_MAX * HID];  // hidden sequence buffer
__device__ float g_seqB[(size_t)MROWS_MAX * HID];  // dec_out
__device__ float g_xpad[(size_t)MROWS_MAX * DIN];  // padded inputs
__device__ float g_hpub[2 * BATCH * HID];          // ping-pong published h
__device__ float g_hT0[BATCH * HID], g_cT0[BATCH * HID];
__device__ float g_hT1[BATCH * HID], g_cT1[BATCH * HID];
__device__ float g_hTd[BATCH * HID], g_cTd[BATCH * HID];
__device__ unsigned g_bar[4];

// ---------------- f32x2 packed-FMA helpers (sm_103a FFMA2) ----------------
__device__ __forceinline__ ull pack2(float x, float y) {
    ull r; asm("mov.b64 %0, {%1, %2};" : "=l"(r) : "f"(x), "f"(y)); return r;
}
__device__ __forceinline__ void fma2(ull& a, ull w, ull h) {
    asm("fma.rn.f32x2 %0, %1, %2, %0;" : "+l"(a) : "l"(w), "l"(h));
}

// ---------------- small utility kernels ----------------
__global__ void reset_bar_kernel(unsigned* bar) {
    if (threadIdx.x < 4) bar[threadIdx.x] = 0u;
}

// dst[b][t][:] = (t==0 || t>Tcopy) ? 0 : src[b][t-1][:]
__global__ void pad_shift_kernel(const float* __restrict__ src, float* __restrict__ dst,
                                 int Tsrc, int Tpad, int Tcopy) {
    long n = (long)BATCH * Tpad * DIN;
    long i = (long)blockIdx.x * blockDim.x + threadIdx.x;
    if (i >= n) return;
    int d = (int)(i % DIN);
    long bt = i / DIN;
    int t = (int)(bt % Tpad);
    int b = (int)(bt / Tpad);
    dst[i] = (t == 0 || t > Tcopy) ? 0.f : src[((long)b * Tsrc + (t - 1)) * DIN + d];
}

__global__ void zero_t0_kernel(float* __restrict__ out) {
    int i = blockIdx.x * blockDim.x + threadIdx.x;
    if (i < BATCH * DIN) {
        int b = i / DIN, d = i % DIN;
        out[(size_t)b * 1024 * DIN + d] = 0.f;
    }
}

// ---------------- fp32 FFMA2 GEMM: C = A(MxK) * W(NxK)^T + b1 + b2 ---------
// 128x128 CTA tile, 256 threads, 8x8 micro tile as 8 rows x 4 column-pairs.
// A stored in smem PRE-DUPLICATED as (a,a) ull pairs -> no MOVs in hot loop.
// Double-buffered smem with register prefetch. K%8==0 required.
// remapT>0: row m -> (b=m/remapT, t=m%remapT) stored at row b*(remapT+1)+t+1.
__global__ void __launch_bounds__(256, 2)
gemm_bias_kernel(const float* __restrict__ A, const float* __restrict__ W,
                 const float* __restrict__ b1, const float* __restrict__ b2,
                 float* __restrict__ C, int M, int N, int K,
                 int relu, int remapT) {
    __shared__ __align__(16) ull   As_d[2][8][130];   // dup (a,a) pairs [k][m]
    __shared__ __align__(16) float Bs[2][8][132];
    const int row0 = blockIdx.y * 128;
    const int col0 = blockIdx.x * 128;
    const int tid = threadIdx.x;
    const int lm = tid >> 1;
    const int lk = (tid & 1) * 4;
    const int tx = tid & 15;
    const int ty = tid >> 4;

    ull acc[8][4];
#pragma unroll
    for (int i = 0; i < 8; i++)
#pragma unroll
        for (int p = 0; p < 4; p++) acc[i][p] = 0ull;

    const int nk = K >> 3;
    const bool aok = (row0 + lm) < M;
    const bool bok = (col0 + lm) < N;
    const float* aptr = A + (size_t)(row0 + lm) * K + lk;
    const float* bptr = W + (size_t)(col0 + lm) * K + lk;

    float4 av = aok ? *(const float4*)aptr : make_float4(0.f, 0.f, 0.f, 0.f);
    float4 bv = bok ? *(const float4*)bptr : make_float4(0.f, 0.f, 0.f, 0.f);
    As_d[0][lk + 0][lm] = pack2(av.x, av.x);
    As_d[0][lk + 1][lm] = pack2(av.y, av.y);
    As_d[0][lk + 2][lm] = pack2(av.z, av.z);
    As_d[0][lk + 3][lm] = pack2(av.w, av.w);
    Bs[0][lk + 0][lm] = bv.x; Bs[0][lk + 1][lm] = bv.y;
    Bs[0][lk + 2][lm] = bv.z; Bs[0][lk + 3][lm] = bv.w;
    __syncthreads();

    for (int ic = 0; ic < nk; ic++) {
        const int cur = ic & 1;
        if (ic + 1 < nk) {
            av = aok ? *(const float4*)(aptr + (ic + 1) * 8) : make_float4(0.f, 0.f, 0.f, 0.f);
            bv = bok ? *(const float4*)(bptr + (ic + 1) * 8) : make_float4(0.f, 0.f, 0.f, 0.f);
        }
#pragma unroll
        for (int k = 0; k < 8; k++) {
            ull ad[8];
            *(ulonglong2*)&ad[0] = *(const ulonglong2*)&As_d[cur][k][ty * 8];
            *(ulonglong2*)&ad[2] = *(const ulonglong2*)&As_d[cur][k][ty * 8 + 2];
            *(ulonglong2*)&ad[4] = *(const ulonglong2*)&As_d[cur][k][ty * 8 + 4];
            *(ulonglong2*)&ad[6] = *(const ulonglong2*)&As_d[cur][k][ty * 8 + 6];
            ull bp[4];
            *(ulonglong2*)&bp[0] = *(const ulonglong2*)&Bs[cur][k][tx * 8];
            *(ulonglong2*)&bp[2] = *(const ulonglong2*)&Bs[cur][k][tx * 8 + 4];
#pragma unroll
            for (int i = 0; i < 8; i++)
#pragma unroll
                for (int p = 0; p < 4; p++) fma2(acc[i][p], bp[p], ad[i]);
        }
        if (ic + 1 < nk) {
            const int nx = cur ^ 1;
            As_d[nx][lk + 0][lm] = pack2(av.x, av.x);
            As_d[nx][lk + 1][lm] = pack2(av.y, av.y);
            As_d[nx][lk + 2][lm] = pack2(av.z, av.z);
            As_d[nx][lk + 3][lm] = pack2(av.w, av.w);
            Bs[nx][lk + 0][lm] = bv.x; Bs[nx][lk + 1][lm] = bv.y;
            Bs[nx][lk + 2][lm] = bv.z; Bs[nx][lk + 3][lm] = bv.w;
        }
        __syncthreads();
    }

#pragma unroll
    for (int i = 0; i < 8; i++) {
        int r = row0 + ty * 8 + i;
        if (r >= M) continue;
        size_t rowbase;
        if (remapT > 0) {
            int bb = r / remapT;
            int tt = r - bb * remapT;
            rowbase = ((size_t)bb * (remapT + 1) + tt + 1) * (size_t)N;
        } else {
            rowbase = (size_t)r * N;
        }
#pragma unroll
        for (int p = 0; p < 4; p++) {
            float2 v = *(float2*)&acc[i][p];
            int c0 = col0 + tx * 8 + 2 * p;
            if (c0 < N) {
                float o = v.x + (b1 ? b1[c0] : 0.f) + (b2 ? b2[c0] : 0.f);
                if (relu) o = fmaxf(o, 0.f);
                C[rowbase + c0] = o;
            }
            if (c0 + 1 < N) {
                float o = v.y + (b1 ? b1[c0 + 1] : 0.f) + (b2 ? b2[c0 + 1] : 0.f);
                if (relu) o = fmaxf(o, 0.f);
                C[rowbase + c0 + 1] = o;
            }
        }
    }
}

// ---------------- persistent LSTM scan (register-resident weights) ---------
// Grid: 128 CTAs = 4 batch-groups(16 batches) x 32 hidden-tiles(16 hidden).
// Proven round-3 combined barrier (atomicAdd poll). gx prefetch for step t+1
// is issued BEFORE the end-of-step barrier (input-only -> race-free) so its
// DRAM latency overlaps the barrier spin.
#define SCAN_H_ULL   (512 * 16)            // h_d: [k][b] dup pairs, 64 KB
#define SCAN_RED_ULL (8 * 32 * 17)         // red: [s][l][b] pad 17, ~34.8 KB
#define SCAN_SMEM_BYTES ((SCAN_H_ULL + SCAN_RED_ULL) * 8)

__device__ __forceinline__ float sigf(float x) { return 1.f / (1.f + expf(-x)); }

__device__ __forceinline__ void group_barrier(unsigned* bar, int bg, unsigned target) {
    __threadfence();          // release: make this CTA's global writes visible
    __syncthreads();
    if (threadIdx.x == 0) {
        atomicAdd(&bar[bg], 1u);
        while (atomicAdd(&bar[bg], 0u) < target) { }
        __threadfence();      // acquire side
    }
    __syncthreads();
}

__global__ void __launch_bounds__(256, 1)
lstm_scan_kernel(const float* __restrict__ gx, const float* __restrict__ Whh,
                 const float* __restrict__ h0, const float* __restrict__ c0,
                 float* __restrict__ hs_out, float* __restrict__ hT_out,
                 float* __restrict__ cT_out, float* __restrict__ hpub,
                 unsigned* __restrict__ bar, int T) {
    extern __shared__ __align__(16) ull smu[];
    ull* h_d = smu;                     // [512][16] : (h,h) pair at [k*16+b]
    ull* red = smu + SCAN_H_ULL;        // [8][32][17]

    const int tid = threadIdx.x;
    const int bg = blockIdx.x >> 5;     // batch group 0..3
    const int ht = blockIdx.x & 31;     // hidden tile 0..31
    const int B0 = bg * 16;
    const int J0 = ht * 16;
    const int w = tid >> 5;             // warp: k-slice
    const int l = tid & 31;             // lane: gate-row pair (2l, 2l+1)

    // ---- load Whh row-pair slice into registers (once) ----
    ull wreg[64];
    {
        const int r0 = 2 * l;
        const int g = r0 >> 4, j = r0 & 15;
        const float* p0 = Whh + ((size_t)(g * 512 + J0 + j)) * 512 + w * 64;
        const float* p1 = p0 + 512;
#pragma unroll
        for (int kk = 0; kk < 64; kk++)
            wreg[kk] = pack2(__ldg(p0 + kk), __ldg(p1 + kk));
    }

    // ---- init states ----
    const int ub = tid >> 4;            // batch within tile (0..15)
    const int uj = tid & 15;            // hidden within tile (0..15)
    float cval = c0 ? c0[(B0 + ub) * 512 + J0 + uj] : 0.f;
    float hval = h0 ? h0[(B0 + ub) * 512 + J0 + uj] : 0.f;
    hpub[32768 + (B0 + ub) * 512 + J0 + uj] = hval;   // parity-1 slot feeds t=0

    unsigned nbar = 1;
    group_barrier(bar, bg, nbar * 32);

    // phase-1 mapping
    const int p1b = tid & 15;
    const int p1k = tid >> 4;           // 0..15

    const float* gxrow = gx + ((size_t)(B0 + ub) * T) * G4 + J0 + uj;
    float* hsrow = hs_out ? hs_out + ((size_t)(B0 + ub) * T) * 512 + J0 + uj : nullptr;

    // prefetch gx for t=0
    float pgi = gxrow[0], pgf = gxrow[512], pgg = gxrow[1024], pgo = gxrow[1536];

    for (int t = 0; t < T; ++t) {
        const float* hsrc = hpub + (((t + 1) & 1) << 15);

        // phase 1: load h (L2-coherent) and store DUPLICATED pairs to smem
#pragma unroll
        for (int i = 0; i < 8; ++i) {
            int kq = p1k + (i << 4);    // 0..127 (float4 index within row)
            float4 hv = __ldcg((const float4*)(hsrc + (B0 + p1b) * 512 + (kq << 2)));
            h_d[((kq << 2) + 0) * 16 + p1b] = pack2(hv.x, hv.x);
            h_d[((kq << 2) + 1) * 16 + p1b] = pack2(hv.y, hv.y);
            h_d[((kq << 2) + 2) * 16 + p1b] = pack2(hv.z, hv.z);
            h_d[((kq << 2) + 3) * 16 + p1b] = pack2(hv.w, hv.w);
        }
        __syncthreads();

        // phase 2: pure FFMA2 stream, weights in regs, h dup-pairs from smem
        ull pacc[16];
#pragma unroll
        for (int b = 0; b < 16; b++) pacc[b] = 0ull;

        const ull* hk = h_d + (w << 6) * 16;
#pragma unroll
        for (int kk = 0; kk < 64; ++kk) {
#pragma unroll
            for (int b2 = 0; b2 < 16; b2 += 2) {
                ulonglong2 h2 = *(const ulonglong2*)(hk + kk * 16 + b2);
                fma2(pacc[b2],     wreg[kk], h2.x);
                fma2(pacc[b2 + 1], wreg[kk], h2.y);
            }
        }

        // phase 3: write row-pair partials
        {
            ull* rp = red + (w * 32 + l) * 17;
#pragma unroll
            for (int b = 0; b < 16; b++) rp[b] = pacc[b];
        }
        __syncthreads();

        // phase 4: reduce 8 k-slices, add gx, LSTM cell (thread = (ub,uj))
        const float* fred = (const float*)red;
        float gsum[4];
#pragma unroll
        for (int g = 0; g < 4; g++) {
            const int ll = g * 8 + (uj >> 1);
            const int comp = uj & 1;
            float v = 0.f;
#pragma unroll
            for (int s2 = 0; s2 < 8; s2++)
                v += fred[2 * (((s2 << 5) + ll) * 17 + ub) + comp];
            gsum[g] = v;
        }
        float gi = gsum[0] + pgi, gf = gsum[1] + pgf;
        float gg = gsum[2] + pgg, go = gsum[3] + pgo;

        float ig = sigf(gi), fg = sigf(gf), og_ = sigf(go), gt = tanhf(gg);
        cval = fg * cval + ig * gt;
        hval = og_ * tanhf(cval);

        hpub[((t & 1) << 15) + (B0 + ub) * 512 + J0 + uj] = hval;
        if (hsrow) { *hsrow = hval; hsrow += 512; }
        gxrow += G4;

        // issue next step's gx prefetch BEFORE the barrier (input-only, safe;
        // bounds-guarded to avoid reading past g_gx on the last step)
        if (t + 1 < T) {
            pgi = gxrow[0]; pgf = gxrow[512];
            pgg = gxrow[1024]; pgo = gxrow[1536];
        }

        ++nbar;
        group_barrier(bar, bg, nbar * 32);
    }

    hT_out[(B0 + ub) * 512 + J0 + uj] = hval;
    cT_out[(B0 + ub) * 512 + J0 + uj] = cval;
}

// ---------------- host orchestration ----------------
static void launch_gemm(const float* A, const float* W, const float* b1, const float* b2,
                        float* C, int M, int N, int K, int relu, int remapT) {
    dim3 grid((N + 127) / 128, (M + 127) / 128);
    gemm_bias_kernel<<<grid, 256>>>(A, W, b1, b2, C, M, N, K, relu, remapT);
}

extern "C" void kernel_launch(void* const* d_in, const int* in_sizes, int n_in,
                              void* d_out, int out_size) {
    (void)in_sizes; (void)n_in; (void)out_size;
    const float* x        = (const float*)d_in[0];
    const float* y        = (const float*)d_in[1];
    const float* eWih0    = (const float*)d_in[2];
    const float* eWhh0    = (const float*)d_in[3];
    const float* ebih0    = (const float*)d_in[4];
    const float* ebhh0    = (const float*)d_in[5];
    const float* eWih1    = (const float*)d_in[6];
    const float* eWhh1    = (const float*)d_in[7];
    const float* ebih1    = (const float*)d_in[8];
    const float* ebhh1    = (const float*)d_in[9];
    const float* dWih0    = (const float*)d_in[10];
    const float* dWhh0    = (const float*)d_in[11];
    const float* dbih0    = (const float*)d_in[12];
    const float* dbhh0    = (const float*)d_in[13];
    const float* dWih1    = (const float*)d_in[14];
    const float* dWhh1    = (const float*)d_in[15];
    const float* dbih1    = (const float*)d_in[16];
    const float* dbhh1    = (const float*)d_in[17];
    const float* clsW1    = (const float*)d_in[18];
    const float* clsb1    = (const float*)d_in[19];
    const float* clsW2    = (const float*)d_in[20];
    const float* clsb2    = (const float*)d_in[21];
    float* out = (float*)d_out;

    float *gx, *seqA, *seqB, *xpad, *hpub, *hT0, *cT0, *hT1, *cT1, *hTd, *cTd;
    unsigned* bar;
    cudaGetSymbolAddress((void**)&gx,   g_gx);
    cudaGetSymbolAddress((void**)&seqA, g_seqA);
    cudaGetSymbolAddress((void**)&seqB, g_seqB);
    cudaGetSymbolAddress((void**)&xpad, g_xpad);
    cudaGetSymbolAddress((void**)&hpub, g_hpub);
    cudaGetSymbolAddress((void**)&hT0,  g_hT0);
    cudaGetSymbolAddress((void**)&cT0,  g_cT0);
    cudaGetSymbolAddress((void**)&hT1,  g_hT1);
    cudaGetSymbolAddress((void**)&cT1,  g_cT1);
    cudaGetSymbolAddress((void**)&hTd,  g_hTd);
    cudaGetSymbolAddress((void**)&cTd,  g_cTd);
    cudaGetSymbolAddress((void**)&bar,  g_bar);

    cudaFuncSetAttribute(lstm_scan_kernel,
                         cudaFuncAttributeMaxDynamicSharedMemorySize, SCAN_SMEM_BYTES);

    const int ME = BATCH * T_ENC;   // 65600
    const int MD = BATCH * T_DEC;   // 65472

    // ---------------- encoder ----------------
    {
        long n = (long)BATCH * T_ENC * DIN;
        pad_shift_kernel<<<(int)((n + 255) / 256), 256>>>(x, xpad, 1024, T_ENC, 1024);
    }
    launch_gemm(xpad, eWih0, ebih0, ebhh0, gx, ME, G4, DIN, 0, 0);
    reset_bar_kernel<<<1, 32>>>(bar);
    lstm_scan_kernel<<<128, 256, SCAN_SMEM_BYTES>>>(gx, eWhh0, nullptr, nullptr,
                                                    seqA, hT0, cT0, hpub, bar, T_ENC);
    launch_gemm(seqA, eWih1, ebih1, ebhh1, gx, ME, G4, HID, 0, 0);
    reset_bar_kernel<<<1, 32>>>(bar);
    lstm_scan_kernel<<<128, 256, SCAN_SMEM_BYTES>>>(gx, eWhh1, nullptr, nullptr,
                                                    nullptr, hT1, cT1, hpub, bar, T_ENC);

    // ---------------- decoder ----------------
    {
        long n = (long)BATCH * T_DEC * DIN;
        pad_shift_kernel<<<(int)((n + 255) / 256), 256>>>(y, xpad, 1024, T_DEC, 1022);
    }
    launch_gemm(xpad, dWih0, dbih0, dbhh0, gx, MD, G4, DIN, 0, 0);
    reset_bar_kernel<<<1, 32>>>(bar);
    lstm_scan_kernel<<<128, 256, SCAN_SMEM_BYTES>>>(gx, dWhh0, hT0, cT0,
                                                    seqA, hTd, cTd, hpub, bar, T_DEC);
    launch_gemm(seqA, dWih1, dbih1, dbhh1, gx, MD, G4, HID, 0, 0);
    reset_bar_kernel<<<1, 32>>>(bar);
    lstm_scan_kernel<<<128, 256, SCAN_SMEM_BYTES>>>(gx, dWhh1, hT1, cT1,
                                                    seqB, hTd, cTd, hpub, bar, T_DEC);

    // ---------------- classifier ----------------
    launch_gemm(seqB, clsW1, clsb1, nullptr, gx, MD, 256, HID, 1, 0);
    launch_gemm(gx, clsW2, clsb2, nullptr, out, MD, DIN, 256, 0, T_DEC);
    zero_t0_kernel<<<(BATCH * DIN + 255) / 256, 256>>>(out);
}

// round 7
// speedup vs baseline: 1.1899x; 1.1899x over previous
#include <cuda_runtime.h>
#include <cuda_bf16.h>
#include <cstdint>

typedef unsigned long long ull;

// ---------------- problem constants ----------------
#define BATCH 64
#define DIN   176
#define HID   512
#define G4    2048          // 4*HID
#define T_ENC 1025          // 1 + 1024
#define T_DEC 1023          // TTGT - 1
#define MROWS_MAX (BATCH * T_ENC)   // 65600
#define MD_ROWS   (BATCH * T_DEC)   // 65472

// ---------------- scratch (static device globals; no cudaMalloc allowed) ----
__device__ float g_gx[(size_t)MROWS_MAX * G4];     // per-layer gx (fp32)
#define ABUF_ROWS (MROWS_MAX + 128)
__device__ __nv_bfloat16 g_AH[(size_t)ABUF_ROWS * 512];   // A operand hi
__device__ __nv_bfloat16 g_AL[(size_t)ABUF_ROWS * 512];   // A operand lo
#define MBUF_ROWS (MD_ROWS + 128)
__device__ __nv_bfloat16 g_MH[(size_t)MBUF_ROWS * 256];   // hmid hi
__device__ __nv_bfloat16 g_ML[(size_t)MBUF_ROWS * 256];   // hmid lo
__device__ __nv_bfloat16 g_WHb[2048 * 512];               // W operand hi
__device__ __nv_bfloat16 g_WLb[2048 * 512];               // W operand lo
__device__ float g_hpub[2 * BATCH * HID];
__device__ float g_hT0[BATCH * HID], g_cT0[BATCH * HID];
__device__ float g_hT1[BATCH * HID], g_cT1[BATCH * HID];
__device__ float g_hTd[BATCH * HID], g_cTd[BATCH * HID];
__device__ unsigned g_bar[4];

// ---------------- helpers ----------------
__device__ __forceinline__ void bf16_split(float v, __nv_bfloat16& hi, __nv_bfloat16& lo) {
    hi = __float2bfloat16(v);
    lo = __float2bfloat16(v - __bfloat162float(hi));
}

// HMMA m16n8k16 bf16 (non-arch-gated PTX; runs on sm_103 base target)
__device__ __forceinline__ void mma16816(float* d, const uint32_t* a, const uint32_t* b) {
    asm volatile(
        "mma.sync.aligned.m16n8k16.row.col.f32.bf16.bf16.f32 "
        "{%0,%1,%2,%3}, {%4,%5,%6,%7}, {%8,%9}, {%0,%1,%2,%3};"
        : "+f"(d[0]), "+f"(d[1]), "+f"(d[2]), "+f"(d[3])
        : "r"(a[0]), "r"(a[1]), "r"(a[2]), "r"(a[3]), "r"(b[0]), "r"(b[1]));
}

// ---------------- small utility kernels ----------------
__global__ void reset_bar_kernel(unsigned* bar) {
    if (threadIdx.x < 4) bar[threadIdx.x] = 0u;
}

// padded-shifted input -> bf16 hi/lo, layout [b][t][192] (cols 176..191 zero)
__global__ void pad_shift_bf16_kernel(const float* __restrict__ src,
                                      __nv_bfloat16* __restrict__ dH,
                                      __nv_bfloat16* __restrict__ dL,
                                      int Tsrc, int Tpad, int Tcopy) {
    long n = (long)BATCH * Tpad * 192;
    long i = (long)blockIdx.x * blockDim.x + threadIdx.x;
    if (i >= n) return;
    int d = (int)(i % 192);
    long bt = i / 192;
    int t = (int)(bt % Tpad);
    int b = (int)(bt / Tpad);
    float v = (d < DIN && t > 0 && t <= Tcopy) ? src[((long)b * Tsrc + (t - 1)) * DIN + d] : 0.f;
    __nv_bfloat16 hi, lo; bf16_split(v, hi, lo);
    dH[i] = hi; dL[i] = lo;
}

// W (N x K fp32) -> WH/WL (Npad x kpad bf16, zero padded)
__global__ void conv_w_kernel(const float* __restrict__ W,
                              __nv_bfloat16* __restrict__ WH, __nv_bfloat16* __restrict__ WL,
                              int N, int K, int kpad, int Npad) {
    long n = (long)Npad * kpad;
    long i = (long)blockIdx.x * blockDim.x + threadIdx.x;
    if (i >= n) return;
    int row = (int)(i / kpad), c = (int)(i % kpad);
    float v = (row < N && c < K) ? W[(size_t)row * K + c] : 0.f;
    __nv_bfloat16 hi, lo; bf16_split(v, hi, lo);
    WH[i] = hi; WL[i] = lo;
}

__global__ void zero_t0_kernel(float* __restrict__ out) {
    int i = blockIdx.x * blockDim.x + threadIdx.x;
    if (i < BATCH * DIN) {
        int b = i / DIN, d = i % DIN;
        out[(size_t)b * 1024 * DIN + d] = 0.f;
    }
}

// ---------------- HMMA GEMM ------------------------------------------
// C(MxN) = A(MxK) * W(NxK)^T + b1 + b2 via bf16 2-way split (3 mma terms).
// CTA = 128x64 tile, 256 threads = 8 warps (4m x 2n), warp tile 32x32.
// K processed in chunks of 32. Smem stride 40 (bank-conflict-free frags).
__global__ void __launch_bounds__(256)
mma_gemm_kernel(const __nv_bfloat16* __restrict__ AH, const __nv_bfloat16* __restrict__ AL,
                const __nv_bfloat16* __restrict__ WH, const __nv_bfloat16* __restrict__ WL,
                int kpad, int nChunks,
                const float* __restrict__ b1, const float* __restrict__ b2,
                float* __restrict__ Cf, __nv_bfloat16* __restrict__ CH,
                __nv_bfloat16* __restrict__ CL,
                int ldC, int M, int Nreal, int relu, int remapT) {
    __shared__ __align__(16) __nv_bfloat16 sAH[128][40];
    __shared__ __align__(16) __nv_bfloat16 sAL[128][40];
    __shared__ __align__(16) __nv_bfloat16 sBH[64][40];
    __shared__ __align__(16) __nv_bfloat16 sBL[64][40];

    const int tid  = threadIdx.x;
    const int wid  = tid >> 5, lane = tid & 31;
    const int g    = lane >> 2, tg = lane & 3;
    const int m0   = (wid & 3) * 32;
    const int n0   = (wid >> 2) * 32;
    const int row0 = blockIdx.y * 128;
    const int col0 = blockIdx.x * 64;

    float d[2][4][4];
#pragma unroll
    for (int mi = 0; mi < 2; mi++)
#pragma unroll
        for (int ni = 0; ni < 4; ni++)
#pragma unroll
            for (int q = 0; q < 4; q++) d[mi][ni][q] = 0.f;

    for (int ch = 0; ch < nChunks; ch++) {
        const int kbase = ch * 32;
        // A: 128 rows x 32 k (2 x uint4 per thread per buffer)
#pragma unroll
        for (int i = 0; i < 2; i++) {
            int idx = tid + (i << 8);
            int r = idx >> 2, seg = idx & 3;
            size_t go = (size_t)(row0 + r) * kpad + kbase + seg * 8;
            *(uint4*)&sAH[r][seg * 8] = __ldg((const uint4*)(AH + go));
            *(uint4*)&sAL[r][seg * 8] = __ldg((const uint4*)(AL + go));
        }
        // B: 64 rows x 32 k (1 x uint4 per thread per buffer)
        {
            int r = tid >> 2, seg = tid & 3;
            size_t go = (size_t)(col0 + r) * kpad + kbase + seg * 8;
            *(uint4*)&sBH[r][seg * 8] = __ldg((const uint4*)(WH + go));
            *(uint4*)&sBL[r][seg * 8] = __ldg((const uint4*)(WL + go));
        }
        __syncthreads();

#pragma unroll
        for (int ks = 0; ks < 2; ks++) {
            const int kb = ks * 16;
            uint32_t aH[2][4], aL[2][4], bH[4][2], bL[4][2];
#pragma unroll
            for (int mi = 0; mi < 2; mi++) {
                int r = m0 + mi * 16 + g;
                aH[mi][0] = *(const uint32_t*)&sAH[r][kb + 2 * tg];
                aH[mi][1] = *(const uint32_t*)&sAH[r + 8][kb + 2 * tg];
                aH[mi][2] = *(const uint32_t*)&sAH[r][kb + 2 * tg + 8];
                aH[mi][3] = *(const uint32_t*)&sAH[r + 8][kb + 2 * tg + 8];
                aL[mi][0] = *(const uint32_t*)&sAL[r][kb + 2 * tg];
                aL[mi][1] = *(const uint32_t*)&sAL[r + 8][kb + 2 * tg];
                aL[mi][2] = *(const uint32_t*)&sAL[r][kb + 2 * tg + 8];
                aL[mi][3] = *(const uint32_t*)&sAL[r + 8][kb + 2 * tg + 8];
            }
#pragma unroll
            for (int ni = 0; ni < 4; ni++) {
                int r = n0 + ni * 8 + g;
                bH[ni][0] = *(const uint32_t*)&sBH[r][kb + 2 * tg];
                bH[ni][1] = *(const uint32_t*)&sBH[r][kb + 2 * tg + 8];
                bL[ni][0] = *(const uint32_t*)&sBL[r][kb + 2 * tg];
                bL[ni][1] = *(const uint32_t*)&sBL[r][kb + 2 * tg + 8];
            }
#pragma unroll
            for (int mi = 0; mi < 2; mi++)
#pragma unroll
                for (int ni = 0; ni < 4; ni++) {
                    mma16816(d[mi][ni], aH[mi], bH[ni]);
                    mma16816(d[mi][ni], aL[mi], bH[ni]);
                    mma16816(d[mi][ni], aH[mi], bL[ni]);
                }
        }
        __syncthreads();
    }

    // epilogue: bias/relu, optional remap, fp32 and/or bf16 hi/lo stores
#pragma unroll
    for (int mi = 0; mi < 2; mi++) {
#pragma unroll
        for (int rr = 0; rr < 2; rr++) {
            int r = row0 + m0 + mi * 16 + g + rr * 8;
            if (r >= M) continue;
            size_t rowbase;
            if (remapT > 0) {
                int bb = r / remapT, tt = r - bb * remapT;
                rowbase = ((size_t)bb * (remapT + 1) + tt + 1) * (size_t)ldC;
            } else {
                rowbase = (size_t)r * ldC;
            }
#pragma unroll
            for (int ni = 0; ni < 4; ni++) {
#pragma unroll
                for (int cc = 0; cc < 2; cc++) {
                    int col = col0 + n0 + ni * 8 + 2 * tg + cc;
                    if (col >= Nreal) continue;
                    float v = d[mi][ni][rr * 2 + cc]
                            + (b1 ? __ldg(b1 + col) : 0.f) + (b2 ? __ldg(b2 + col) : 0.f);
                    if (relu) v = fmaxf(v, 0.f);
                    if (Cf) Cf[rowbase + col] = v;
                    if (CH) {
                        __nv_bfloat16 hi, lo; bf16_split(v, hi, lo);
                        CH[rowbase + col] = hi;
                        CL[rowbase + col] = lo;
                    }
                }
            }
        }
    }
}

// ---------------- persistent LSTM scan (round-3 proven, bf16 hi/lo out) ---
#define SCAN_H_ULL   (512 * 16)
#define SCAN_RED_ULL (8 * 32 * 17)
#define SCAN_SMEM_BYTES ((SCAN_H_ULL + SCAN_RED_ULL) * 8)

__device__ __forceinline__ ull pack2(float x, float y) {
    ull r; asm("mov.b64 %0, {%1, %2};" : "=l"(r) : "f"(x), "f"(y)); return r;
}
__device__ __forceinline__ void fma2(ull& a, ull w, ull h) {
    asm("fma.rn.f32x2 %0, %1, %2, %0;" : "+l"(a) : "l"(w), "l"(h));
}
__device__ __forceinline__ float sigf(float x) { return 1.f / (1.f + expf(-x)); }

__device__ __forceinline__ void group_barrier(unsigned* bar, int bg, unsigned target) {
    __threadfence();
    __syncthreads();
    if (threadIdx.x == 0) {
        atomicAdd(&bar[bg], 1u);
        while (atomicAdd(&bar[bg], 0u) < target) { }
        __threadfence();
    }
    __syncthreads();
}

__global__ void __launch_bounds__(256, 1)
lstm_scan_kernel(const float* __restrict__ gx, const float* __restrict__ Whh,
                 const float* __restrict__ h0, const float* __restrict__ c0,
                 __nv_bfloat16* __restrict__ hsH, __nv_bfloat16* __restrict__ hsL,
                 float* __restrict__ hT_out, float* __restrict__ cT_out,
                 float* __restrict__ hpub, unsigned* __restrict__ bar, int T) {
    extern __shared__ __align__(16) ull smu[];
    ull* h_d = smu;
    ull* red = smu + SCAN_H_ULL;

    const int tid = threadIdx.x;
    const int bg = blockIdx.x >> 5;
    const int ht = blockIdx.x & 31;
    const int B0 = bg * 16;
    const int J0 = ht * 16;
    const int w = tid >> 5;
    const int l = tid & 31;

    ull wreg[64];
    {
        const int r0 = 2 * l;
        const int g = r0 >> 4, j = r0 & 15;
        const float* p0 = Whh + ((size_t)(g * 512 + J0 + j)) * 512 + w * 64;
        const float* p1 = p0 + 512;
#pragma unroll
        for (int kk = 0; kk < 64; kk++)
            wreg[kk] = pack2(__ldg(p0 + kk), __ldg(p1 + kk));
    }

    const int ub = tid >> 4;
    const int uj = tid & 15;
    float cval = c0 ? c0[(B0 + ub) * 512 + J0 + uj] : 0.f;
    float hval = h0 ? h0[(B0 + ub) * 512 + J0 + uj] : 0.f;
    hpub[32768 + (B0 + ub) * 512 + J0 + uj] = hval;

    unsigned nbar = 1;
    group_barrier(bar, bg, nbar * 32);

    const int p1b = tid & 15;
    const int p1k = tid >> 4;

    const float* gxrow = gx + ((size_t)(B0 + ub) * T) * G4 + J0 + uj;
    __nv_bfloat16* hH = hsH ? hsH + ((size_t)(B0 + ub) * T) * 512 + J0 + uj : nullptr;
    __nv_bfloat16* hL = hsL ? hsL + ((size_t)(B0 + ub) * T) * 512 + J0 + uj : nullptr;

    for (int t = 0; t < T; ++t) {
        float pgi = gxrow[0], pgf = gxrow[512], pgg = gxrow[1024], pgo = gxrow[1536];

        const float* hsrc = hpub + (((t + 1) & 1) << 15);
#pragma unroll
        for (int i = 0; i < 8; ++i) {
            int kq = p1k + (i << 4);
            float4 hv = __ldcg((const float4*)(hsrc + (B0 + p1b) * 512 + (kq << 2)));
            h_d[((kq << 2) + 0) * 16 + p1b] = pack2(hv.x, hv.x);
            h_d[((kq << 2) + 1) * 16 + p1b] = pack2(hv.y, hv.y);
            h_d[((kq << 2) + 2) * 16 + p1b] = pack2(hv.z, hv.z);
            h_d[((kq << 2) + 3) * 16 + p1b] = pack2(hv.w, hv.w);
        }
        __syncthreads();

        ull pacc[16];
#pragma unroll
        for (int b = 0; b < 16; b++) pacc[b] = 0ull;

        const ull* hk = h_d + (w << 6) * 16;
#pragma unroll
        for (int kk = 0; kk < 64; ++kk) {
#pragma unroll
            for (int b2 = 0; b2 < 16; b2 += 2) {
                ulonglong2 h2 = *(const ulonglong2*)(hk + kk * 16 + b2);
                fma2(pacc[b2],     wreg[kk], h2.x);
                fma2(pacc[b2 + 1], wreg[kk], h2.y);
            }
        }

        {
            ull* rp = red + (w * 32 + l) * 17;
#pragma unroll
            for (int b = 0; b < 16; b++) rp[b] = pacc[b];
        }
        __syncthreads();

        const float* fred = (const float*)red;
        float gsum[4];
#pragma unroll
        for (int g = 0; g < 4; g++) {
            const int ll = g * 8 + (uj >> 1);
            const int comp = uj & 1;
            float v = 0.f;
#pragma unroll
            for (int s2 = 0; s2 < 8; s2++)
                v += fred[2 * (((s2 << 5) + ll) * 17 + ub) + comp];
            gsum[g] = v;
        }
        float gi = gsum[0] + pgi, gf = gsum[1] + pgf;
        float gg = gsum[2] + pgg, go = gsum[3] + pgo;

        float ig = sigf(gi), fg = sigf(gf), og_ = sigf(go), gt = tanhf(gg);
        cval = fg * cval + ig * gt;
        hval = og_ * tanhf(cval);

        hpub[((t & 1) << 15) + (B0 + ub) * 512 + J0 + uj] = hval;
        if (hH) {
            __nv_bfloat16 hi, lo; bf16_split(hval, hi, lo);
            *hH = hi; *hL = lo; hH += 512; hL += 512;
        }
        gxrow += G4;

        ++nbar;
        group_barrier(bar, bg, nbar * 32);
    }

    hT_out[(B0 + ub) * 512 + J0 + uj] = hval;
    cT_out[(B0 + ub) * 512 + J0 + uj] = cval;
}

// ---------------- host orchestration ----------------
static __nv_bfloat16 *s_AH, *s_AL, *s_MH, *s_ML, *s_WH, *s_WL;

static void launch_mma(const __nv_bfloat16* AH, const __nv_bfloat16* AL,
                       int kpad, const float* b1, const float* b2,
                       float* Cf, __nv_bfloat16* CH, __nv_bfloat16* CL,
                       int ldC, int M, int Nreal, int relu, int remapT) {
    int mt = (M + 127) / 128;
    int nt = (Nreal + 63) / 64;
    int nChunks = kpad / 32;
    mma_gemm_kernel<<<dim3(nt, mt), 256>>>(
        AH, AL, s_WH, s_WL, kpad, nChunks, b1, b2, Cf, CH, CL, ldC, M, Nreal, relu, remapT);
}

static void launch_convw(const float* W, int N, int K, int kpad) {
    int Npad = ((N + 63) / 64) * 64;
    long n = (long)Npad * kpad;
    conv_w_kernel<<<(int)((n + 255) / 256), 256>>>(W, s_WH, s_WL, N, K, kpad, Npad);
}

extern "C" void kernel_launch(void* const* d_in, const int* in_sizes, int n_in,
                              void* d_out, int out_size) {
    (void)in_sizes; (void)n_in; (void)out_size;
    const float* x     = (const float*)d_in[0];
    const float* y     = (const float*)d_in[1];
    const float* eWih0 = (const float*)d_in[2];
    const float* eWhh0 = (const float*)d_in[3];
    const float* ebih0 = (const float*)d_in[4];
    const float* ebhh0 = (const float*)d_in[5];
    const float* eWih1 = (const float*)d_in[6];
    const float* eWhh1 = (const float*)d_in[7];
    const float* ebih1 = (const float*)d_in[8];
    const float* ebhh1 = (const float*)d_in[9];
    const float* dWih0 = (const float*)d_in[10];
    const float* dWhh0 = (const float*)d_in[11];
    const float* dbih0 = (const float*)d_in[12];
    const float* dbhh0 = (const float*)d_in[13];
    const float* dWih1 = (const float*)d_in[14];
    const float* dWhh1 = (const float*)d_in[15];
    const float* dbih1 = (const float*)d_in[16];
    const float* dbhh1 = (const float*)d_in[17];
    const float* clsW1 = (const float*)d_in[18];
    const float* clsb1 = (const float*)d_in[19];
    const float* clsW2 = (const float*)d_in[20];
    const float* clsb2 = (const float*)d_in[21];
    float* out = (float*)d_out;

    float *gx, *hpub, *hT0, *cT0, *hT1, *cT1, *hTd, *cTd;
    unsigned* bar;
    cudaGetSymbolAddress((void**)&gx,   g_gx);
    cudaGetSymbolAddress((void**)&hpub, g_hpub);
    cudaGetSymbolAddress((void**)&hT0,  g_hT0);
    cudaGetSymbolAddress((void**)&cT0,  g_cT0);
    cudaGetSymbolAddress((void**)&hT1,  g_hT1);
    cudaGetSymbolAddress((void**)&cT1,  g_cT1);
    cudaGetSymbolAddress((void**)&hTd,  g_hTd);
    cudaGetSymbolAddress((void**)&cTd,  g_cTd);
    cudaGetSymbolAddress((void**)&bar,  g_bar);
    cudaGetSymbolAddress((void**)&s_AH, g_AH);
    cudaGetSymbolAddress((void**)&s_AL, g_AL);
    cudaGetSymbolAddress((void**)&s_MH, g_MH);
    cudaGetSymbolAddress((void**)&s_ML, g_ML);
    cudaGetSymbolAddress((void**)&s_WH, g_WHb);
    cudaGetSymbolAddress((void**)&s_WL, g_WLb);

    cudaFuncSetAttribute(lstm_scan_kernel,
                         cudaFuncAttributeMaxDynamicSharedMemorySize, SCAN_SMEM_BYTES);

    const int ME  = MROWS_MAX;   // 65600
    const int MDN = MD_ROWS;     // 65472

    // ---------------- encoder ----------------
    {
        long n = (long)BATCH * T_ENC * 192;
        pad_shift_bf16_kernel<<<(int)((n + 255) / 256), 256>>>(x, s_AH, s_AL, 1024, T_ENC, 1024);
    }
    launch_convw(eWih0, G4, DIN, 192);
    launch_mma(s_AH, s_AL, 192, ebih0, ebhh0, gx, nullptr, nullptr, G4, ME, G4, 0, 0);
    reset_bar_kernel<<<1, 32>>>(bar);
    lstm_scan_kernel<<<128, 256, SCAN_SMEM_BYTES>>>(gx, eWhh0, nullptr, nullptr,
                                                    s_AH, s_AL, hT0, cT0, hpub, bar, T_ENC);
    launch_convw(eWih1, G4, HID, 512);
    launch_mma(s_AH, s_AL, 512, ebih1, ebhh1, gx, nullptr, nullptr, G4, ME, G4, 0, 0);
    reset_bar_kernel<<<1, 32>>>(bar);
    lstm_scan_kernel<<<128, 256, SCAN_SMEM_BYTES>>>(gx, eWhh1, nullptr, nullptr,
                                                    nullptr, nullptr, hT1, cT1, hpub, bar, T_ENC);

    // ---------------- decoder ----------------
    {
        long n = (long)BATCH * T_DEC * 192;
        pad_shift_bf16_kernel<<<(int)((n + 255) / 256), 256>>>(y, s_AH, s_AL, 1024, T_DEC, 1022);
    }
    launch_convw(dWih0, G4, DIN, 192);
    launch_mma(s_AH, s_AL, 192, dbih0, dbhh0, gx, nullptr, nullptr, G4, MDN, G4, 0, 0);
    reset_bar_kernel<<<1, 32>>>(bar);
    lstm_scan_kernel<<<128, 256, SCAN_SMEM_BYTES>>>(gx, dWhh0, hT0, cT0,
                                                    s_AH, s_AL, hTd, cTd, hpub, bar, T_DEC);
    launch_convw(dWih1, G4, HID, 512);
    launch_mma(s_AH, s_AL, 512, dbih1, dbhh1, gx, nullptr, nullptr, G4, MDN, G4, 0, 0);
    reset_bar_kernel<<<1, 32>>>(bar);
    lstm_scan_kernel<<<128, 256, SCAN_SMEM_BYTES>>>(gx, dWhh1, hT1, cT1,
                                                    s_AH, s_AL, hTd, cTd, hpub, bar, T_DEC);

    // ---------------- classifier ----------------
    launch_convw(clsW1, 256, HID, 512);
    launch_mma(s_AH, s_AL, 512, clsb1, nullptr, nullptr, s_MH, s_ML, 256, MDN, 256, 1, 0);
    launch_convw(clsW2, DIN, 256, 256);
    launch_mma(s_MH, s_ML, 256, clsb2, nullptr, out, nullptr, nullptr, DIN, MDN, DIN, 0, T_DEC);
    zero_t0_kernel<<<(BATCH * DIN + 255) / 256, 256>>>(out);
}

// round 8
// speedup vs baseline: 1.2116x; 1.0183x over previous
#include <cuda_runtime.h>
#include <cuda_bf16.h>
#include <cstdint>

typedef unsigned long long ull;

// ---------------- problem constants ----------------
#define BATCH 64
#define DIN   176
#define HID   512
#define G4    2048          // 4*HID
#define T_ENC 1025          // 1 + 1024
#define T_DEC 1023          // TTGT - 1
#define MROWS_MAX (BATCH * T_ENC)   // 65600
#define MD_ROWS   (BATCH * T_DEC)   // 65472

// ---------------- scratch (static device globals; no cudaMalloc allowed) ----
__device__ float g_gx[(size_t)MROWS_MAX * G4];     // per-layer gx (fp32)
#define ABUF_ROWS (MROWS_MAX + 128)
__device__ __nv_bfloat16 g_AH[(size_t)ABUF_ROWS * 512];   // A operand hi
__device__ __nv_bfloat16 g_AL[(size_t)ABUF_ROWS * 512];   // A operand lo
#define MBUF_ROWS (MD_ROWS + 128)
__device__ __nv_bfloat16 g_MH[(size_t)MBUF_ROWS * 256];   // hmid hi
__device__ __nv_bfloat16 g_ML[(size_t)MBUF_ROWS * 256];   // hmid lo
__device__ __nv_bfloat16 g_WHb[2048 * 512];               // W operand hi
__device__ __nv_bfloat16 g_WLb[2048 * 512];               // W operand lo
__device__ float g_hpub[2 * BATCH * HID];
__device__ float g_hT0[BATCH * HID], g_cT0[BATCH * HID];
__device__ float g_hT1[BATCH * HID], g_cT1[BATCH * HID];
__device__ float g_hTd[BATCH * HID], g_cTd[BATCH * HID];
__device__ unsigned g_bar[4];

// ---------------- helpers ----------------
__device__ __forceinline__ void bf16_split(float v, __nv_bfloat16& hi, __nv_bfloat16& lo) {
    hi = __float2bfloat16(v);
    lo = __float2bfloat16(v - __bfloat162float(hi));
}

__device__ __forceinline__ uint32_t smem_to_u32(const void* p) {
    uint32_t a;
    asm("{ .reg .u64 t; cvta.to.shared.u64 t, %1; cvt.u32.u64 %0, t; }" : "=r"(a) : "l"(p));
    return a;
}

// HMMA m16n8k16 bf16 (non-arch-gated PTX; runs on sm_103 base target)
__device__ __forceinline__ void mma16816(float* d, const uint32_t* a, const uint32_t* b) {
    asm volatile(
        "mma.sync.aligned.m16n8k16.row.col.f32.bf16.bf16.f32 "
        "{%0,%1,%2,%3}, {%4,%5,%6,%7}, {%8,%9}, {%0,%1,%2,%3};"
        : "+f"(d[0]), "+f"(d[1]), "+f"(d[2]), "+f"(d[3])
        : "r"(a[0]), "r"(a[1]), "r"(a[2]), "r"(a[3]), "r"(b[0]), "r"(b[1]));
}

// cp.async 16B (LDGSTS; sm_80 PTX, non-gated)
__device__ __forceinline__ void cpasync16(uint32_t s, const void* g) {
    asm volatile("cp.async.cg.shared.global [%0], [%1], 16;" :: "r"(s), "l"(g));
}
#define CP_COMMIT() asm volatile("cp.async.commit_group;" ::: "memory")
#define CP_WAIT1()  asm volatile("cp.async.wait_group 1;" ::: "memory")

// ---------------- small utility kernels ----------------
__global__ void reset_bar_kernel(unsigned* bar) {
    if (threadIdx.x < 4) bar[threadIdx.x] = 0u;
}

// padded-shifted input -> bf16 hi/lo, layout [b][t][192] (cols 176..191 zero)
__global__ void pad_shift_bf16_kernel(const float* __restrict__ src,
                                      __nv_bfloat16* __restrict__ dH,
                                      __nv_bfloat16* __restrict__ dL,
                                      int Tsrc, int Tpad, int Tcopy) {
    long n = (long)BATCH * Tpad * 192;
    long i = (long)blockIdx.x * blockDim.x + threadIdx.x;
    if (i >= n) return;
    int d = (int)(i % 192);
    long bt = i / 192;
    int t = (int)(bt % Tpad);
    int b = (int)(bt / Tpad);
    float v = (d < DIN && t > 0 && t <= Tcopy) ? src[((long)b * Tsrc + (t - 1)) * DIN + d] : 0.f;
    __nv_bfloat16 hi, lo; bf16_split(v, hi, lo);
    dH[i] = hi; dL[i] = lo;
}

// W (N x K fp32) -> WH/WL (Npad x kpad bf16, zero padded)
__global__ void conv_w_kernel(const float* __restrict__ W,
                              __nv_bfloat16* __restrict__ WH, __nv_bfloat16* __restrict__ WL,
                              int N, int K, int kpad, int Npad) {
    long n = (long)Npad * kpad;
    long i = (long)blockIdx.x * blockDim.x + threadIdx.x;
    if (i >= n) return;
    int row = (int)(i / kpad), c = (int)(i % kpad);
    float v = (row < N && c < K) ? W[(size_t)row * K + c] : 0.f;
    __nv_bfloat16 hi, lo; bf16_split(v, hi, lo);
    WH[i] = hi; WL[i] = lo;
}

__global__ void zero_t0_kernel(float* __restrict__ out) {
    int i = blockIdx.x * blockDim.x + threadIdx.x;
    if (i < BATCH * DIN) {
        int b = i / DIN, d = i % DIN;
        out[(size_t)b * 1024 * DIN + d] = 0.f;
    }
}

// ---------------- HMMA GEMM (cp.async 2-stage pipelined) -------------------
// C(MxN) = A(MxK) * W(NxK)^T + b1 + b2 via bf16 2-way split (3 mma terms).
// CTA = 128x64 tile, 256 threads = 8 warps (4m x 2n), warp tile 32x32.
// K in chunks of 32; double-buffered smem filled by cp.async.
// Stage layout (bf16 elems): AH[128*40] AL[128*40] BH[64*40] BL[64*40]
#define SOFF_AL  5120
#define SOFF_BH  10240
#define SOFF_BL  12800
#define STG_ELEMS 15360
#define MMA_SMEM_BYTES (2 * STG_ELEMS * 2)   // 61440

__global__ void __launch_bounds__(256)
mma_gemm_kernel(const __nv_bfloat16* __restrict__ AH, const __nv_bfloat16* __restrict__ AL,
                const __nv_bfloat16* __restrict__ WH, const __nv_bfloat16* __restrict__ WL,
                int kpad, int nChunks,
                const float* __restrict__ b1, const float* __restrict__ b2,
                float* __restrict__ Cf, __nv_bfloat16* __restrict__ CH,
                __nv_bfloat16* __restrict__ CL,
                int ldC, int M, int Nreal, int relu, int remapT) {
    extern __shared__ __align__(16) __nv_bfloat16 smbuf[];
    const uint32_t sb = smem_to_u32(smbuf);

    const int tid  = threadIdx.x;
    const int wid  = tid >> 5, lane = tid & 31;
    const int g    = lane >> 2, tg = lane & 3;
    const int m0   = (wid & 3) * 32;
    const int n0   = (wid >> 2) * 32;
    const int row0 = blockIdx.y * 128;
    const int col0 = blockIdx.x * 64;

    // per-thread load coordinates
    const int ar0 = tid >> 2, aseg = tid & 3;        // A: rows ar0, ar0+64
    const int br  = tid >> 2, bseg = tid & 3;        // B: row br

    float d[2][4][4];
#pragma unroll
    for (int mi = 0; mi < 2; mi++)
#pragma unroll
        for (int ni = 0; ni < 4; ni++)
#pragma unroll
            for (int q = 0; q < 4; q++) d[mi][ni][q] = 0.f;

    // ---- async chunk loader ----
    auto load_chunk = [&](int ch, int stg) {
        const int kbase = ch * 32;
        const uint32_t base = sb + stg * (STG_ELEMS * 2);
#pragma unroll
        for (int i = 0; i < 2; i++) {
            int r = ar0 + i * 64;
            size_t go = (size_t)(row0 + r) * kpad + kbase + aseg * 8;
            uint32_t so = base + (r * 40 + aseg * 8) * 2;
            cpasync16(so, AH + go);
            cpasync16(so + SOFF_AL * 2, AL + go);
        }
        {
            size_t go = (size_t)(col0 + br) * kpad + kbase + bseg * 8;
            uint32_t so = base + (SOFF_BH + br * 40 + bseg * 8) * 2;
            cpasync16(so, WH + go);
            cpasync16(so + (SOFF_BL - SOFF_BH) * 2, WL + go);
        }
    };

    load_chunk(0, 0);
    CP_COMMIT();

    for (int ch = 0; ch < nChunks; ch++) {
        const int cur = ch & 1;
        if (ch + 1 < nChunks) load_chunk(ch + 1, cur ^ 1);
        CP_COMMIT();
        CP_WAIT1();
        __syncthreads();

        const __nv_bfloat16* sAH = smbuf + cur * STG_ELEMS;
        const __nv_bfloat16* sAL = sAH + SOFF_AL;
        const __nv_bfloat16* sBH = smbuf + cur * STG_ELEMS + SOFF_BH;
        const __nv_bfloat16* sBL = smbuf + cur * STG_ELEMS + SOFF_BL;

#pragma unroll
        for (int ks = 0; ks < 2; ks++) {
            const int kb = ks * 16;
            uint32_t aH[2][4], aL[2][4], bH[4][2], bL[4][2];
#pragma unroll
            for (int mi = 0; mi < 2; mi++) {
                int r = m0 + mi * 16 + g;
                aH[mi][0] = *(const uint32_t*)&sAH[r * 40 + kb + 2 * tg];
                aH[mi][1] = *(const uint32_t*)&sAH[(r + 8) * 40 + kb + 2 * tg];
                aH[mi][2] = *(const uint32_t*)&sAH[r * 40 + kb + 2 * tg + 8];
                aH[mi][3] = *(const uint32_t*)&sAH[(r + 8) * 40 + kb + 2 * tg + 8];
                aL[mi][0] = *(const uint32_t*)&sAL[r * 40 + kb + 2 * tg];
                aL[mi][1] = *(const uint32_t*)&sAL[(r + 8) * 40 + kb + 2 * tg];
                aL[mi][2] = *(const uint32_t*)&sAL[r * 40 + kb + 2 * tg + 8];
                aL[mi][3] = *(const uint32_t*)&sAL[(r + 8) * 40 + kb + 2 * tg + 8];
            }
#pragma unroll
            for (int ni = 0; ni < 4; ni++) {
                int r = n0 + ni * 8 + g;
                bH[ni][0] = *(const uint32_t*)&sBH[r * 40 + kb + 2 * tg];
                bH[ni][1] = *(const uint32_t*)&sBH[r * 40 + kb + 2 * tg + 8];
                bL[ni][0] = *(const uint32_t*)&sBL[r * 40 + kb + 2 * tg];
                bL[ni][1] = *(const uint32_t*)&sBL[r * 40 + kb + 2 * tg + 8];
            }
#pragma unroll
            for (int mi = 0; mi < 2; mi++)
#pragma unroll
                for (int ni = 0; ni < 4; ni++) {
                    mma16816(d[mi][ni], aH[mi], bH[ni]);
                    mma16816(d[mi][ni], aL[mi], bH[ni]);
                    mma16816(d[mi][ni], aH[mi], bL[ni]);
                }
        }
        __syncthreads();
    }

    // epilogue: bias/relu, optional remap, fp32 and/or bf16 hi/lo stores
#pragma unroll
    for (int mi = 0; mi < 2; mi++) {
#pragma unroll
        for (int rr = 0; rr < 2; rr++) {
            int r = row0 + m0 + mi * 16 + g + rr * 8;
            if (r >= M) continue;
            size_t rowbase;
            if (remapT > 0) {
                int bb = r / remapT, tt = r - bb * remapT;
                rowbase = ((size_t)bb * (remapT + 1) + tt + 1) * (size_t)ldC;
            } else {
                rowbase = (size_t)r * ldC;
            }
#pragma unroll
            for (int ni = 0; ni < 4; ni++) {
#pragma unroll
                for (int cc = 0; cc < 2; cc++) {
                    int col = col0 + n0 + ni * 8 + 2 * tg + cc;
                    if (col >= Nreal) continue;
                    float v = d[mi][ni][rr * 2 + cc]
                            + (b1 ? __ldg(b1 + col) : 0.f) + (b2 ? __ldg(b2 + col) : 0.f);
                    if (relu) v = fmaxf(v, 0.f);
                    if (Cf) Cf[rowbase + col] = v;
                    if (CH) {
                        __nv_bfloat16 hi, lo; bf16_split(v, hi, lo);
                        CH[rowbase + col] = hi;
                        CL[rowbase + col] = lo;
                    }
                }
            }
        }
    }
}

// ---------------- persistent LSTM scan (round-3 proven, bf16 hi/lo out) ---
#define SCAN_H_ULL   (512 * 16)
#define SCAN_RED_ULL (8 * 32 * 17)
#define SCAN_SMEM_BYTES ((SCAN_H_ULL + SCAN_RED_ULL) * 8)

__device__ __forceinline__ ull pack2(float x, float y) {
    ull r; asm("mov.b64 %0, {%1, %2};" : "=l"(r) : "f"(x), "f"(y)); return r;
}
__device__ __forceinline__ void fma2(ull& a, ull w, ull h) {
    asm("fma.rn.f32x2 %0, %1, %2, %0;" : "+l"(a) : "l"(w), "l"(h));
}
__device__ __forceinline__ float sigf(float x) { return 1.f / (1.f + expf(-x)); }

__device__ __forceinline__ void group_barrier(unsigned* bar, int bg, unsigned target) {
    __threadfence();
    __syncthreads();
    if (threadIdx.x == 0) {
        atomicAdd(&bar[bg], 1u);
        while (atomicAdd(&bar[bg], 0u) < target) { }
        __threadfence();
    }
    __syncthreads();
}

__global__ void __launch_bounds__(256, 1)
lstm_scan_kernel(const float* __restrict__ gx, const float* __restrict__ Whh,
                 const float* __restrict__ h0, const float* __restrict__ c0,
                 __nv_bfloat16* __restrict__ hsH, __nv_bfloat16* __restrict__ hsL,
                 float* __restrict__ hT_out, float* __restrict__ cT_out,
                 float* __restrict__ hpub, unsigned* __restrict__ bar, int T) {
    extern __shared__ __align__(16) ull smu[];
    ull* h_d = smu;
    ull* red = smu + SCAN_H_ULL;

    const int tid = threadIdx.x;
    const int bg = blockIdx.x >> 5;
    const int ht = blockIdx.x & 31;
    const int B0 = bg * 16;
    const int J0 = ht * 16;
    const int w = tid >> 5;
    const int l = tid & 31;

    ull wreg[64];
    {
        const int r0 = 2 * l;
        const int g = r0 >> 4, j = r0 & 15;
        const float* p0 = Whh + ((size_t)(g * 512 + J0 + j)) * 512 + w * 64;
        const float* p1 = p0 + 512;
#pragma unroll
        for (int kk = 0; kk < 64; kk++)
            wreg[kk] = pack2(__ldg(p0 + kk), __ldg(p1 + kk));
    }

    const int ub = tid >> 4;
    const int uj = tid & 15;
    float cval = c0 ? c0[(B0 + ub) * 512 + J0 + uj] : 0.f;
    float hval = h0 ? h0[(B0 + ub) * 512 + J0 + uj] : 0.f;
    hpub[32768 + (B0 + ub) * 512 + J0 + uj] = hval;

    unsigned nbar = 1;
    group_barrier(bar, bg, nbar * 32);

    const int p1b = tid & 15;
    const int p1k = tid >> 4;

    const float* gxrow = gx + ((size_t)(B0 + ub) * T) * G4 + J0 + uj;
    __nv_bfloat16* hH = hsH ? hsH + ((size_t)(B0 + ub) * T) * 512 + J0 + uj : nullptr;
    __nv_bfloat16* hL = hsL ? hsL + ((size_t)(B0 + ub) * T) * 512 + J0 + uj : nullptr;

    for (int t = 0; t < T; ++t) {
        float pgi = gxrow[0], pgf = gxrow[512], pgg = gxrow[1024], pgo = gxrow[1536];

        const float* hsrc = hpub + (((t + 1) & 1) << 15);
#pragma unroll
        for (int i = 0; i < 8; ++i) {
            int kq = p1k + (i << 4);
            float4 hv = __ldcg((const float4*)(hsrc + (B0 + p1b) * 512 + (kq << 2)));
            h_d[((kq << 2) + 0) * 16 + p1b] = pack2(hv.x, hv.x);
            h_d[((kq << 2) + 1) * 16 + p1b] = pack2(hv.y, hv.y);
            h_d[((kq << 2) + 2) * 16 + p1b] = pack2(hv.z, hv.z);
            h_d[((kq << 2) + 3) * 16 + p1b] = pack2(hv.w, hv.w);
        }
        __syncthreads();

        ull pacc[16];
#pragma unroll
        for (int b = 0; b < 16; b++) pacc[b] = 0ull;

        const ull* hk = h_d + (w << 6) * 16;
#pragma unroll
        for (int kk = 0; kk < 64; ++kk) {
#pragma unroll
            for (int b2 = 0; b2 < 16; b2 += 2) {
                ulonglong2 h2 = *(const ulonglong2*)(hk + kk * 16 + b2);
                fma2(pacc[b2],     wreg[kk], h2.x);
                fma2(pacc[b2 + 1], wreg[kk], h2.y);
            }
        }

        {
            ull* rp = red + (w * 32 + l) * 17;
#pragma unroll
            for (int b = 0; b < 16; b++) rp[b] = pacc[b];
        }
        __syncthreads();

        const float* fred = (const float*)red;
        float gsum[4];
#pragma unroll
        for (int g = 0; g < 4; g++) {
            const int ll = g * 8 + (uj >> 1);
            const int comp = uj & 1;
            float v = 0.f;
#pragma unroll
            for (int s2 = 0; s2 < 8; s2++)
                v += fred[2 * (((s2 << 5) + ll) * 17 + ub) + comp];
            gsum[g] = v;
        }
        float gi = gsum[0] + pgi, gf = gsum[1] + pgf;
        float gg = gsum[2] + pgg, go = gsum[3] + pgo;

        float ig = sigf(gi), fg = sigf(gf), og_ = sigf(go), gt = tanhf(gg);
        cval = fg * cval + ig * gt;
        hval = og_ * tanhf(cval);

        hpub[((t & 1) << 15) + (B0 + ub) * 512 + J0 + uj] = hval;
        if (hH) {
            __nv_bfloat16 hi, lo; bf16_split(hval, hi, lo);
            *hH = hi; *hL = lo; hH += 512; hL += 512;
        }
        gxrow += G4;

        ++nbar;
        group_barrier(bar, bg, nbar * 32);
    }

    hT_out[(B0 + ub) * 512 + J0 + uj] = hval;
    cT_out[(B0 + ub) * 512 + J0 + uj] = cval;
}

// ---------------- host orchestration ----------------
static __nv_bfloat16 *s_AH, *s_AL, *s_MH, *s_ML, *s_WH, *s_WL;

static void launch_mma(const __nv_bfloat16* AH, const __nv_bfloat16* AL,
                       int kpad, const float* b1, const float* b2,
                       float* Cf, __nv_bfloat16* CH, __nv_bfloat16* CL,
                       int ldC, int M, int Nreal, int relu, int remapT) {
    int mt = (M + 127) / 128;
    int nt = (Nreal + 63) / 64;
    int nChunks = kpad / 32;
    mma_gemm_kernel<<<dim3(nt, mt), 256, MMA_SMEM_BYTES>>>(
        AH, AL, s_WH, s_WL, kpad, nChunks, b1, b2, Cf, CH, CL, ldC, M, Nreal, relu, remapT);
}

static void launch_convw(const float* W, int N, int K, int kpad) {
    int Npad = ((N + 63) / 64) * 64;
    long n = (long)Npad * kpad;
    conv_w_kernel<<<(int)((n + 255) / 256), 256>>>(W, s_WH, s_WL, N, K, kpad, Npad);
}

extern "C" void kernel_launch(void* const* d_in, const int* in_sizes, int n_in,
                              void* d_out, int out_size) {
    (void)in_sizes; (void)n_in; (void)out_size;
    const float* x     = (const float*)d_in[0];
    const float* y     = (const float*)d_in[1];
    const float* eWih0 = (const float*)d_in[2];
    const float* eWhh0 = (const float*)d_in[3];
    const float* ebih0 = (const float*)d_in[4];
    const float* ebhh0 = (const float*)d_in[5];
    const float* eWih1 = (const float*)d_in[6];
    const float* eWhh1 = (const float*)d_in[7];
    const float* ebih1 = (const float*)d_in[8];
    const float* ebhh1 = (const float*)d_in[9];
    const float* dWih0 = (const float*)d_in[10];
    const float* dWhh0 = (const float*)d_in[11];
    const float* dbih0 = (const float*)d_in[12];
    const float* dbhh0 = (const float*)d_in[13];
    const float* dWih1 = (const float*)d_in[14];
    const float* dWhh1 = (const float*)d_in[15];
    const float* dbih1 = (const float*)d_in[16];
    const float* dbhh1 = (const float*)d_in[17];
    const float* clsW1 = (const float*)d_in[18];
    const float* clsb1 = (const float*)d_in[19];
    const float* clsW2 = (const float*)d_in[20];
    const float* clsb2 = (const float*)d_in[21];
    float* out = (float*)d_out;

    float *gx, *hpub, *hT0, *cT0, *hT1, *cT1, *hTd, *cTd;
    unsigned* bar;
    cudaGetSymbolAddress((void**)&gx,   g_gx);
    cudaGetSymbolAddress((void**)&hpub, g_hpub);
    cudaGetSymbolAddress((void**)&hT0,  g_hT0);
    cudaGetSymbolAddress((void**)&cT0,  g_cT0);
    cudaGetSymbolAddress((void**)&hT1,  g_hT1);
    cudaGetSymbolAddress((void**)&cT1,  g_cT1);
    cudaGetSymbolAddress((void**)&hTd,  g_hTd);
    cudaGetSymbolAddress((void**)&cTd,  g_cTd);
    cudaGetSymbolAddress((void**)&bar,  g_bar);
    cudaGetSymbolAddress((void**)&s_AH, g_AH);
    cudaGetSymbolAddress((void**)&s_AL, g_AL);
    cudaGetSymbolAddress((void**)&s_MH, g_MH);
    cudaGetSymbolAddress((void**)&s_ML, g_ML);
    cudaGetSymbolAddress((void**)&s_WH, g_WHb);
    cudaGetSymbolAddress((void**)&s_WL, g_WLb);

    cudaFuncSetAttribute(lstm_scan_kernel,
                         cudaFuncAttributeMaxDynamicSharedMemorySize, SCAN_SMEM_BYTES);
    cudaFuncSetAttribute(mma_gemm_kernel,
                         cudaFuncAttributeMaxDynamicSharedMemorySize, MMA_SMEM_BYTES);

    const int ME  = MROWS_MAX;   // 65600
    const int MDN = MD_ROWS;     // 65472

    // ---------------- encoder ----------------
    {
        long n = (long)BATCH * T_ENC * 192;
        pad_shift_bf16_kernel<<<(int)((n + 255) / 256), 256>>>(x, s_AH, s_AL, 1024, T_ENC, 1024);
    }
    launch_convw(eWih0, G4, DIN, 192);
    launch_mma(s_AH, s_AL, 192, ebih0, ebhh0, gx, nullptr, nullptr, G4, ME, G4, 0, 0);
    reset_bar_kernel<<<1, 32>>>(bar);
    lstm_scan_kernel<<<128, 256, SCAN_SMEM_BYTES>>>(gx, eWhh0, nullptr, nullptr,
                                                    s_AH, s_AL, hT0, cT0, hpub, bar, T_ENC);
    launch_convw(eWih1, G4, HID, 512);
    launch_mma(s_AH, s_AL, 512, ebih1, ebhh1, gx, nullptr, nullptr, G4, ME, G4, 0, 0);
    reset_bar_kernel<<<1, 32>>>(bar);
    lstm_scan_kernel<<<128, 256, SCAN_SMEM_BYTES>>>(gx, eWhh1, nullptr, nullptr,
                                                    nullptr, nullptr, hT1, cT1, hpub, bar, T_ENC);

    // ---------------- decoder ----------------
    {
        long n = (long)BATCH * T_DEC * 192;
        pad_shift_bf16_kernel<<<(int)((n + 255) / 256), 256>>>(y, s_AH, s_AL, 1024, T_DEC, 1022);
    }
    launch_convw(dWih0, G4, DIN, 192);
    launch_mma(s_AH, s_AL, 192, dbih0, dbhh0, gx, nullptr, nullptr, G4, MDN, G4, 0, 0);
    reset_bar_kernel<<<1, 32>>>(bar);
    lstm_scan_kernel<<<128, 256, SCAN_SMEM_BYTES>>>(gx, dWhh0, hT0, cT0,
                                                    s_AH, s_AL, hTd, cTd, hpub, bar, T_DEC);
    launch_convw(dWih1, G4, HID, 512);
    launch_mma(s_AH, s_AL, 512, dbih1, dbhh1, gx, nullptr, nullptr, G4, MDN, G4, 0, 0);
    reset_bar_kernel<<<1, 32>>>(bar);
    lstm_scan_kernel<<<128, 256, SCAN_SMEM_BYTES>>>(gx, dWhh1, hT1, cT1,
                                                    s_AH, s_AL, hTd, cTd, hpub, bar, T_DEC);

    // ---------------- classifier ----------------
    launch_convw(clsW1, 256, HID, 512);
    launch_mma(s_AH, s_AL, 512, clsb1, nullptr, nullptr, s_MH, s_ML, 256, MDN, 256, 1, 0);
    launch_convw(clsW2, DIN, 256, 256);
    launch_mma(s_MH, s_ML, 256, clsb2, nullptr, out, nullptr, nullptr, DIN, MDN, DIN, 0, T_DEC);
    zero_t0_kernel<<<(BATCH * DIN + 255) / 256, 256>>>(out);
}